// round 10
// baseline (speedup 1.0000x reference)
#include <cuda_runtime.h>

// Vanilla tanh RNN: B=4096, T=2048, I=4, H=20, O=4.
// R10: THREE independent batch-chains per warp (9 batches/warp), 4 warps/CTA =
// exactly 1 warp per SMSP (uniform balance -- R8's failure was SMSP imbalance,
// not the ILP idea). Per-chain structure = R7 (proven): 3 batches x 10 lanes,
// 30/32 live, plain-layout SMEM ping-pong exchange (syncwarp-free), f32x2 dot
// packed over j, tanh.approx, register x-prefetch rings (PF=4 per chain).
// One compiler memory fence per ROUND so ptxas interleaves the 3 chains.

#define B_TOTAL 4096
#define T_STEPS 2048
#define H_DIM   20
#define O_DIM   4
#define WARPS_CTA 4
#define NB_WARP   9
#define CTA_THREADS (WARPS_CTA * 32)
#define GRID 114             // ceil(4096 / 36)
#define PF 4                 // x prefetch depth per chain (steps)

typedef unsigned long long u64;

__device__ __forceinline__ u64 pack2(float lo, float hi) {
    u64 r; asm("mov.b64 %0, {%1,%2};" : "=l"(r) : "f"(lo), "f"(hi)); return r;
}
__device__ __forceinline__ void unpack2(u64 v, float& lo, float& hi) {
    asm("mov.b64 {%0,%1}, %2;" : "=f"(lo), "=f"(hi) : "l"(v));
}
__device__ __forceinline__ u64 fma2(u64 a, u64 b, u64 c) {
    u64 d; asm("fma.rn.f32x2 %0, %1, %2, %3;" : "=l"(d) : "l"(a), "l"(b), "l"(c)); return d;
}
__device__ __forceinline__ u64 add2(u64 a, u64 b) {
    u64 d; asm("add.rn.f32x2 %0, %1, %2;" : "=l"(d) : "l"(a), "l"(b)); return d;
}
__device__ __forceinline__ float tanha(float x) {
    float r; asm("tanh.approx.f32 %0, %1;" : "=f"(r) : "f"(x)); return r;
}

// One step of ONE chain. Branch-free, unconditional store (sOff routes dead
// lanes to scratch). No fence here -- caller fences once per round so the
// three chains' instructions can interleave.
__device__ __forceinline__ void rnn_step(
    const float* src, float* dst,
    int g, int sOff, ulonglong2 xv,
    const u64* __restrict__ W0, const u64* __restrict__ W1,
    ulonglong2 Wi0, ulonglong2 Wi1, u64 seed0, u64 seed1)
{
    const ulonglong2* hsrc = reinterpret_cast<const ulonglong2*>(src + g * H_DIM);
    ulonglong2 hv0 = hsrc[0];
    ulonglong2 hv1 = hsrc[1];
    ulonglong2 hv2 = hsrc[2];
    ulonglong2 hv3 = hsrc[3];
    ulonglong2 hv4 = hsrc[4];

    const u64 z = pack2(0.f, 0.f);
    u64 a0 = fma2(xv.x, Wi0.x, seed0);
    u64 b0 = fma2(xv.y, Wi0.y, z);
    u64 a1 = fma2(xv.x, Wi1.x, seed1);
    u64 b1 = fma2(xv.y, Wi1.y, z);

    a0 = fma2(hv0.x, W0[0], a0);  b0 = fma2(hv0.y, W0[1], b0);
    a1 = fma2(hv0.x, W1[0], a1);  b1 = fma2(hv0.y, W1[1], b1);
    a0 = fma2(hv1.x, W0[2], a0);  b0 = fma2(hv1.y, W0[3], b0);
    a1 = fma2(hv1.x, W1[2], a1);  b1 = fma2(hv1.y, W1[3], b1);
    a0 = fma2(hv2.x, W0[4], a0);  b0 = fma2(hv2.y, W0[5], b0);
    a1 = fma2(hv2.x, W1[4], a1);  b1 = fma2(hv2.y, W1[5], b1);
    a0 = fma2(hv3.x, W0[6], a0);  b0 = fma2(hv3.y, W0[7], b0);
    a1 = fma2(hv3.x, W1[6], a1);  b1 = fma2(hv3.y, W1[7], b1);
    a0 = fma2(hv4.x, W0[8], a0);  b0 = fma2(hv4.y, W0[9], b0);
    a1 = fma2(hv4.x, W1[8], a1);  b1 = fma2(hv4.y, W1[9], b1);

    u64 s0 = add2(a0, b0);
    u64 s1 = add2(a1, b1);

    float l0, l1, m0, m1;
    unpack2(s0, l0, l1);
    unpack2(s1, m0, m1);
    float t0 = tanha(l0 + l1);
    float t1 = tanha(m0 + m1);

    *reinterpret_cast<u64*>(dst + sOff) = pack2(t0, t1);
}

__global__ void __launch_bounds__(CTA_THREADS, 1)
rnn_tanh_kernel(
    const float* __restrict__ x,     const float* __restrict__ h0,
    const float* __restrict__ W_ih,  const float* __restrict__ W_hh,
    const float* __restrict__ b_ih,  const float* __restrict__ b_hh,
    const float* __restrict__ fc_w,  const float* __restrict__ fc_b,
    float* __restrict__ out)
{
    __shared__ __align__(128) float sm[WARPS_CTA][3][2][64];  // [warp][chain][pp][64]

    const int lane = threadIdx.x & 31;
    const int w    = threadIdx.x >> 5;
    const int gw   = blockIdx.x * WARPS_CTA + w;
    const int base = gw * NB_WARP;
    if (base >= B_TOTAL) return;

    const bool live = (lane < 30);
    const int  g    = live ? (lane / 10) : 2;
    const int  p    = live ? (lane % 10) : (lane - 30);
    const int  o0   = 2 * p;
    const int  sOff = live ? (g * H_DIM + o0) : (60 + (lane - 30) * 2);

    const int bA = base + g;
    const int bB = base + 3 + g;
    const int bC = base + 6 + g;
    const int bAc = (bA < B_TOTAL) ? bA : (B_TOTAL - 1);
    const int bBc = (bB < B_TOTAL) ? bB : (B_TOTAL - 1);
    const int bCc = (bC < B_TOTAL) ? bC : (B_TOTAL - 1);

    // ---- per-thread weights (packed over j; shared by all chains) ----
    const u64* whh = reinterpret_cast<const u64*>(W_hh);
    u64 W0[10], W1[10];
    #pragma unroll
    for (int q = 0; q < 10; q++) {
        W0[q] = __ldg(&whh[o0 * 10 + q]);
        W1[q] = __ldg(&whh[(o0 + 1) * 10 + q]);
    }
    const ulonglong2* wih = reinterpret_cast<const ulonglong2*>(W_ih);
    ulonglong2 Wi0 = __ldg(&wih[o0]);
    ulonglong2 Wi1 = __ldg(&wih[o0 + 1]);
    const float bias0 = __ldg(&b_ih[o0])     + __ldg(&b_hh[o0]);
    const float bias1 = __ldg(&b_ih[o0 + 1]) + __ldg(&b_hh[o0 + 1]);
    const u64 seed0 = pack2(bias0, 0.f);
    const u64 seed1 = pack2(bias1, 0.f);

    float* A0 = &sm[w][0][0][0];  float* A1 = &sm[w][0][1][0];
    float* B0 = &sm[w][1][0][0];  float* B1 = &sm[w][1][1][0];
    float* C0 = &sm[w][2][0][0];  float* C1 = &sm[w][2][1][0];

    // ---- init h (plain layout) into ping buffers ----
    {
        const float2* h2 = reinterpret_cast<const float2*>(h0);
        float2 ha = __ldg(&h2[bAc * (H_DIM / 2) + p]);
        float2 hb = __ldg(&h2[bBc * (H_DIM / 2) + p]);
        float2 hc = __ldg(&h2[bCc * (H_DIM / 2) + p]);
        *reinterpret_cast<u64*>(A0 + sOff) = pack2(ha.x, ha.y);
        *reinterpret_cast<u64*>(B0 + sOff) = pack2(hb.x, hb.y);
        *reinterpret_cast<u64*>(C0 + sOff) = pack2(hc.x, hc.y);
    }
    __syncwarp();

    // x rings, one per chain. x[b][t] = 16B.
    const ulonglong2* xpA = reinterpret_cast<const ulonglong2*>(x) + (size_t)bAc * T_STEPS;
    const ulonglong2* xpB = reinterpret_cast<const ulonglong2*>(x) + (size_t)bBc * T_STEPS;
    const ulonglong2* xpC = reinterpret_cast<const ulonglong2*>(x) + (size_t)bCc * T_STEPS;
    ulonglong2 xa[PF], xb[PF], xc[PF];
    #pragma unroll
    for (int q = 0; q < PF; q++) {
        xa[q] = __ldg(&xpA[q]); xb[q] = __ldg(&xpB[q]); xc[q] = __ldg(&xpC[q]);
    }

    // Main loop: prefetch unclamped (t+q+PF <= T-1 for t <= T-2*PF).
    for (int t = 0; t < T_STEPS - PF; t += PF) {
        #pragma unroll
        for (int q = 0; q < PF; q++) {
            ulonglong2 xvA = xa[q], xvB = xb[q], xvC = xc[q];
            xa[q] = __ldg(&xpA[t + q + PF]);
            xb[q] = __ldg(&xpB[t + q + PF]);
            xc[q] = __ldg(&xpC[t + q + PF]);
            if (q & 1) {
                rnn_step(A1, A0, g, sOff, xvA, W0, W1, Wi0, Wi1, seed0, seed1);
                rnn_step(B1, B0, g, sOff, xvB, W0, W1, Wi0, Wi1, seed0, seed1);
                rnn_step(C1, C0, g, sOff, xvC, W0, W1, Wi0, Wi1, seed0, seed1);
            } else {
                rnn_step(A0, A1, g, sOff, xvA, W0, W1, Wi0, Wi1, seed0, seed1);
                rnn_step(B0, B1, g, sOff, xvB, W0, W1, Wi0, Wi1, seed0, seed1);
                rnn_step(C0, C1, g, sOff, xvC, W0, W1, Wi0, Wi1, seed0, seed1);
            }
            asm volatile("" ::: "memory");   // fence once per round
        }
    }
    // Epilogue: last PF rounds, no prefetch.
    #pragma unroll
    for (int q = 0; q < PF; q++) {
        if (q & 1) {
            rnn_step(A1, A0, g, sOff, xa[q], W0, W1, Wi0, Wi1, seed0, seed1);
            rnn_step(B1, B0, g, sOff, xb[q], W0, W1, Wi0, Wi1, seed0, seed1);
            rnn_step(C1, C0, g, sOff, xc[q], W0, W1, Wi0, Wi1, seed0, seed1);
        } else {
            rnn_step(A0, A1, g, sOff, xa[q], W0, W1, Wi0, Wi1, seed0, seed1);
            rnn_step(B0, B1, g, sOff, xb[q], W0, W1, Wi0, Wi1, seed0, seed1);
            rnn_step(C0, C1, g, sOff, xc[q], W0, W1, Wi0, Wi1, seed0, seed1);
        }
        asm volatile("" ::: "memory");
    }

    // Final h in ping buffers (T_STEPS even). Linear head: live lanes with p < 4.
    __syncwarp();
    if (live && p < O_DIM) {
        float accA = __ldg(&fc_b[p]);
        float accB = accA, accC = accA;
        const float* hfA = A0 + g * H_DIM;
        const float* hfB = B0 + g * H_DIM;
        const float* hfC = C0 + g * H_DIM;
        #pragma unroll
        for (int j = 0; j < H_DIM; j++) {
            float wj = __ldg(&fc_w[p * H_DIM + j]);
            accA = fmaf(hfA[j], wj, accA);
            accB = fmaf(hfB[j], wj, accB);
            accC = fmaf(hfC[j], wj, accC);
        }
        if (bA < B_TOTAL) out[bA * O_DIM + p] = accA;
        if (bB < B_TOTAL) out[bB * O_DIM + p] = accB;
        if (bC < B_TOTAL) out[bC * O_DIM + p] = accC;
    }
}

extern "C" void kernel_launch(void* const* d_in, const int* in_sizes, int n_in,
                              void* d_out, int out_size)
{
    const float* x    = (const float*)d_in[0];
    const float* h0   = (const float*)d_in[1];
    const float* W_ih = (const float*)d_in[2];
    const float* W_hh = (const float*)d_in[3];
    const float* b_ih = (const float*)d_in[4];
    const float* b_hh = (const float*)d_in[5];
    const float* fc_w = (const float*)d_in[6];
    const float* fc_b = (const float*)d_in[7];
    float* out = (float*)d_out;

    rnn_tanh_kernel<<<GRID, CTA_THREADS>>>(x, h0, W_ih, W_hh, b_ih, b_hh,
                                           fc_w, fc_b, out);
}

// round 11
// speedup vs baseline: 2.3003x; 2.3003x over previous
#include <cuda_runtime.h>
#include <cuda_fp16.h>

// Vanilla tanh RNN: B=4096, T=2048, I=4, H=20, O=4.
// R11: fp16x2 recurrence on the HFMA2 pipe (rt=2 -> 2x MAC rate of any fp32 path;
// fp32 f32x2 measured rt=4, so R7 was already fma-pipe bound at ~280cyc/step).
// Shell = R7 (proven): 10 warps/CTA, 3 batches/warp (30/32 lanes live), grid 148,
// syncwarp-free warp-private SMEM ping-pong, 8-deep fp32 x register prefetch ring.
// h stored as 10x fp16x2 per batch (40B). Dot = 24 HFMA2/lane/step; horizontal
// combine via PRMT+HADD2; single tanh.approx.f16x2 MUFU; STS.32 exchange.

#define B_TOTAL 4096
#define T_STEPS 2048
#define H_DIM   20
#define O_DIM   4
#define WARPS_CTA 10
#define CTA_THREADS (WARPS_CTA * 32)
#define GRID 148
#define PF 8                        // x prefetch depth (steps)
#define HSTRIDE 12                  // u32 stride per batch in smem (10 used + pad)

typedef unsigned int u32;
typedef unsigned long long u64;

__device__ __forceinline__ void unpack2(u64 v, float& lo, float& hi) {
    asm("mov.b64 {%0,%1}, %2;" : "=f"(lo), "=f"(hi) : "l"(v));
}
// d = { lo: lo, hi: hi } as fp16x2
__device__ __forceinline__ u32 cvt2h(float hi, float lo) {
    u32 d; asm("cvt.rn.f16x2.f32 %0, %1, %2;" : "=r"(d) : "f"(hi), "f"(lo)); return d;
}
__device__ __forceinline__ u32 hfma2(u32 a, u32 b, u32 c) {
    u32 d; asm("fma.rn.f16x2 %0, %1, %2, %3;" : "=r"(d) : "r"(a), "r"(b), "r"(c)); return d;
}
__device__ __forceinline__ u32 hadd2(u32 a, u32 b) {
    u32 d; asm("add.rn.f16x2 %0, %1, %2;" : "=r"(d) : "r"(a), "r"(b)); return d;
}
__device__ __forceinline__ u32 prmt(u32 a, u32 b, u32 sel) {
    u32 d; asm("prmt.b32 %0, %1, %2, %3;" : "=r"(d) : "r"(a), "r"(b), "r"(sel)); return d;
}
__device__ __forceinline__ u32 tanh2(u32 a) {
    u32 d; asm("tanh.approx.f16x2 %0, %1;" : "=r"(d) : "r"(a)); return d;
}

// One step for one thread (batch g, outputs o0=2p, o0+1).
// h in smem as fp16x2 words: batch g at u32 offset g*HSTRIDE, word q = {h_2q, h_2q+1}.
__device__ __forceinline__ void rnn_step(
    const u32* __restrict__ src, u32* __restrict__ dst,
    int g, int sOff, ulonglong2 xv,
    const u32* __restrict__ W0, const u32* __restrict__ W1,
    u32 Wi0a, u32 Wi0b, u32 Wi1a, u32 Wi1b, u32 seed0, u32 seed1)
{
    const u32* hb = src + g * HSTRIDE;
    uint4 hA = *reinterpret_cast<const uint4*>(hb);       // q0..3
    uint4 hB = *reinterpret_cast<const uint4*>(hb + 4);   // q4..7
    uint2 hC = *reinterpret_cast<const uint2*>(hb + 8);   // q8..9

    // x -> fp16x2 (xproj overlaps the LDS latency; h-independent)
    float x0, x1, x2, x3;
    unpack2(xv.x, x0, x1);
    unpack2(xv.y, x2, x3);
    u32 xh0 = cvt2h(x1, x0);
    u32 xh1 = cvt2h(x3, x2);

    // chains: a = bias + q0..4, b = xproj + q5..9 (per output)
    u32 a0 = hfma2(xh0, Wi0a, seed0);   // seed0 = {lo=bias0, hi=0}
    a0 = hfma2(xh1, Wi0b, a0);
    u32 a1 = hfma2(xh0, Wi1a, seed1);
    a1 = hfma2(xh1, Wi1b, a1);
    u32 b0 = 0, b1 = 0;

    a0 = hfma2(hA.x, W0[0], a0);  b0 = hfma2(hB.y, W0[5], b0);
    a1 = hfma2(hA.x, W1[0], a1);  b1 = hfma2(hB.y, W1[5], b1);
    a0 = hfma2(hA.y, W0[1], a0);  b0 = hfma2(hB.z, W0[6], b0);
    a1 = hfma2(hA.y, W1[1], a1);  b1 = hfma2(hB.z, W1[6], b1);
    a0 = hfma2(hA.z, W0[2], a0);  b0 = hfma2(hB.w, W0[7], b0);
    a1 = hfma2(hA.z, W1[2], a1);  b1 = hfma2(hB.w, W1[7], b1);
    a0 = hfma2(hA.w, W0[3], a0);  b0 = hfma2(hC.x, W0[8], b0);
    a1 = hfma2(hA.w, W1[3], a1);  b1 = hfma2(hC.x, W1[8], b1);
    a0 = hfma2(hB.x, W0[4], a0);  b0 = hfma2(hC.y, W0[9], b0);
    a1 = hfma2(hB.x, W1[4], a1);  b1 = hfma2(hC.y, W1[9], b1);

    u32 A = hadd2(a0, b0);          // {p, q}: o0pre = p + q
    u32 B = hadd2(a1, b1);          // {r, s}: o1pre = r + s
    u32 C = prmt(A, B, 0x5410);     // {p, r}
    u32 D = prmt(A, B, 0x7632);     // {q, s}
    u32 E = hadd2(C, D);            // {o0pre, o1pre}
    u32 hn = tanh2(E);              // {h_o0, h_o1} fp16x2

    dst[sOff] = hn;                 // unconditional STS.32 (dead lanes -> scratch)
    asm volatile("" ::: "memory");  // pin program order of smem ops
}

__global__ void __launch_bounds__(CTA_THREADS, 1)
rnn_tanh_kernel(
    const float* __restrict__ x,     const float* __restrict__ h0,
    const float* __restrict__ W_ih,  const float* __restrict__ W_hh,
    const float* __restrict__ b_ih,  const float* __restrict__ b_hh,
    const float* __restrict__ fc_w,  const float* __restrict__ fc_b,
    float* __restrict__ out)
{
    __shared__ __align__(16) u32 sm[WARPS_CTA][2][40];   // [warp][pp][3*12 + scratch]

    const int lane = threadIdx.x & 31;
    const int w    = threadIdx.x >> 5;
    const int gw   = blockIdx.x * WARPS_CTA + w;
    if (gw * 3 >= B_TOTAL) return;

    const bool live = (lane < 30);
    const int  g    = live ? (lane / 10) : 2;
    const int  p    = live ? (lane % 10) : (lane - 30);
    const int  b    = gw * 3 + g;
    const int  bc   = (b < B_TOTAL) ? b : (B_TOTAL - 1);
    const int  o0   = 2 * p;
    const int  sOff = live ? (g * HSTRIDE + p) : (38 + (lane - 30));  // scratch 38/39

    // ---- per-thread weights: fp16x2 packed over j ----
    u32 W0[10], W1[10];
    #pragma unroll
    for (int q = 0; q < 10; q++) {
        W0[q] = cvt2h(__ldg(&W_hh[o0 * H_DIM + 2 * q + 1]),
                      __ldg(&W_hh[o0 * H_DIM + 2 * q]));
        W1[q] = cvt2h(__ldg(&W_hh[(o0 + 1) * H_DIM + 2 * q + 1]),
                      __ldg(&W_hh[(o0 + 1) * H_DIM + 2 * q]));
    }
    const u32 Wi0a = cvt2h(__ldg(&W_ih[o0 * 4 + 1]), __ldg(&W_ih[o0 * 4 + 0]));
    const u32 Wi0b = cvt2h(__ldg(&W_ih[o0 * 4 + 3]), __ldg(&W_ih[o0 * 4 + 2]));
    const u32 Wi1a = cvt2h(__ldg(&W_ih[(o0 + 1) * 4 + 1]), __ldg(&W_ih[(o0 + 1) * 4 + 0]));
    const u32 Wi1b = cvt2h(__ldg(&W_ih[(o0 + 1) * 4 + 3]), __ldg(&W_ih[(o0 + 1) * 4 + 2]));
    const u32 seed0 = cvt2h(0.f, __ldg(&b_ih[o0])     + __ldg(&b_hh[o0]));
    const u32 seed1 = cvt2h(0.f, __ldg(&b_ih[o0 + 1]) + __ldg(&b_hh[o0 + 1]));

    u32* bufA = &sm[w][0][0];
    u32* bufB = &sm[w][1][0];

    // ---- init h (fp16x2) into buffer A ----
    {
        const float2* h2 = reinterpret_cast<const float2*>(h0);
        float2 hv = __ldg(&h2[bc * (H_DIM / 2) + p]);
        bufA[sOff] = cvt2h(hv.y, hv.x);
    }
    __syncwarp();

    // x[b][t] = 4 floats = one ulonglong2; fp32 8-deep register prefetch ring.
    const ulonglong2* xp = reinterpret_cast<const ulonglong2*>(x) + (size_t)bc * T_STEPS;
    ulonglong2 xbuf[PF];
    #pragma unroll
    for (int q = 0; q < PF; q++) xbuf[q] = __ldg(&xp[q]);

    for (int t = 0; t < T_STEPS - PF; t += PF) {
        #pragma unroll
        for (int q = 0; q < PF; q++) {
            ulonglong2 xv = xbuf[q];
            xbuf[q] = __ldg(&xp[t + q + PF]);
            if (q & 1)
                rnn_step(bufB, bufA, g, sOff, xv, W0, W1, Wi0a, Wi0b, Wi1a, Wi1b, seed0, seed1);
            else
                rnn_step(bufA, bufB, g, sOff, xv, W0, W1, Wi0a, Wi0b, Wi1a, Wi1b, seed0, seed1);
        }
    }
    #pragma unroll
    for (int q = 0; q < PF; q++) {
        if (q & 1)
            rnn_step(bufB, bufA, g, sOff, xbuf[q], W0, W1, Wi0a, Wi0b, Wi1a, Wi1b, seed0, seed1);
        else
            rnn_step(bufA, bufB, g, sOff, xbuf[q], W0, W1, Wi0a, Wi0b, Wi1a, Wi1b, seed0, seed1);
    }

    // Final h in bufA (T_STEPS even). Linear head in fp32 from fp16 h.
    __syncwarp();
    if (live && p < O_DIM && b < B_TOTAL) {
        const u32* hb = bufA + g * HSTRIDE;
        float acc = __ldg(&fc_b[p]);
        #pragma unroll
        for (int q = 0; q < 10; q++) {
            float2 hv = __half22float2(*reinterpret_cast<const __half2*>(&hb[q]));
            acc = fmaf(hv.x, __ldg(&fc_w[p * H_DIM + 2 * q]),     acc);
            acc = fmaf(hv.y, __ldg(&fc_w[p * H_DIM + 2 * q + 1]), acc);
        }
        out[b * O_DIM + p] = acc;
    }
}

extern "C" void kernel_launch(void* const* d_in, const int* in_sizes, int n_in,
                              void* d_out, int out_size)
{
    const float* x    = (const float*)d_in[0];
    const float* h0   = (const float*)d_in[1];
    const float* W_ih = (const float*)d_in[2];
    const float* W_hh = (const float*)d_in[3];
    const float* b_ih = (const float*)d_in[4];
    const float* b_hh = (const float*)d_in[5];
    const float* fc_w = (const float*)d_in[6];
    const float* fc_b = (const float*)d_in[7];
    float* out = (float*)d_out;

    rnn_tanh_kernel<<<GRID, CTA_THREADS>>>(x, h0, W_ih, W_hh, b_ih, b_hh,
                                           fc_w, fc_b, out);
}

// round 12
// speedup vs baseline: 2.3542x; 1.0234x over previous
#include <cuda_runtime.h>
#include <cuda_fp16.h>

// Vanilla tanh RNN: B=4096, T=2048, I=4, H=20, O=4.
// R11 base: fp16x2 recurrence on HFMA2 (rt=2), 10 warps/CTA, 3 batches/warp
// (30/32 lanes), warp-private SMEM ping-pong, syncwarp-free, PF=8 x ring.
// R12: (a) per-warp phase STAGGER before the loop to break warp convoying
// (all warps otherwise stall on LDS in lockstep -> fma pipe idles in gaps);
// (b) dot chains rebalanced to depth 6+6; (c) fence at TOP of step so the
// next x LDG can hoist into the previous step's latency shadow.

#define B_TOTAL 4096
#define T_STEPS 2048
#define H_DIM   20
#define O_DIM   4
#define WARPS_CTA 10
#define CTA_THREADS (WARPS_CTA * 32)
#define GRID 148
#define PF 8                        // x prefetch depth (steps)
#define HSTRIDE 12                  // u32 stride per batch in smem

typedef unsigned int u32;
typedef unsigned long long u64;

__device__ __forceinline__ void unpack2(u64 v, float& lo, float& hi) {
    asm("mov.b64 {%0,%1}, %2;" : "=f"(lo), "=f"(hi) : "l"(v));
}
__device__ __forceinline__ u32 cvt2h(float hi, float lo) {
    u32 d; asm("cvt.rn.f16x2.f32 %0, %1, %2;" : "=r"(d) : "f"(hi), "f"(lo)); return d;
}
__device__ __forceinline__ u32 hfma2(u32 a, u32 b, u32 c) {
    u32 d; asm("fma.rn.f16x2 %0, %1, %2, %3;" : "=r"(d) : "r"(a), "r"(b), "r"(c)); return d;
}
__device__ __forceinline__ u32 hadd2(u32 a, u32 b) {
    u32 d; asm("add.rn.f16x2 %0, %1, %2;" : "=r"(d) : "r"(a), "r"(b)); return d;
}
__device__ __forceinline__ u32 prmt(u32 a, u32 b, u32 sel) {
    u32 d; asm("prmt.b32 %0, %1, %2, %3;" : "=r"(d) : "r"(a), "r"(b), "r"(sel)); return d;
}
__device__ __forceinline__ u32 tanh2(u32 a) {
    u32 d; asm("tanh.approx.f16x2 %0, %1;" : "=r"(d) : "r"(a)); return d;
}

__device__ __forceinline__ void rnn_step(
    const u32* __restrict__ src, u32* __restrict__ dst,
    int g, int sOff, ulonglong2 xv,
    const u32* __restrict__ W0, const u32* __restrict__ W1,
    u32 Wi0a, u32 Wi0b, u32 Wi1a, u32 Wi1b, u32 seed0, u32 seed1)
{
    asm volatile("" ::: "memory");  // order prior STS before this step's LDS;
                                    // lets next x LDG hoist into previous step.
    const u32* hb = src + g * HSTRIDE;
    uint4 hA = *reinterpret_cast<const uint4*>(hb);       // q0..3
    uint4 hB = *reinterpret_cast<const uint4*>(hb + 4);   // q4..7
    uint2 hC = *reinterpret_cast<const uint2*>(hb + 8);   // q8..9

    float x0, x1, x2, x3;
    unpack2(xv.x, x0, x1);
    unpack2(xv.y, x2, x3);
    u32 xh0 = cvt2h(x1, x0);
    u32 xh1 = cvt2h(x3, x2);

    // Balanced chains, depth 6 each: a = bias + x01 + q0..4, b = x23 + q5..9.
    u32 a0 = hfma2(xh0, Wi0a, seed0);
    u32 b0 = hfma2(xh1, Wi0b, 0u);
    u32 a1 = hfma2(xh0, Wi1a, seed1);
    u32 b1 = hfma2(xh1, Wi1b, 0u);

    a0 = hfma2(hA.x, W0[0], a0);  b0 = hfma2(hB.y, W0[5], b0);
    a1 = hfma2(hA.x, W1[0], a1);  b1 = hfma2(hB.y, W1[5], b1);
    a0 = hfma2(hA.y, W0[1], a0);  b0 = hfma2(hB.z, W0[6], b0);
    a1 = hfma2(hA.y, W1[1], a1);  b1 = hfma2(hB.z, W1[6], b1);
    a0 = hfma2(hA.z, W0[2], a0);  b0 = hfma2(hB.w, W0[7], b0);
    a1 = hfma2(hA.z, W1[2], a1);  b1 = hfma2(hB.w, W1[7], b1);
    a0 = hfma2(hA.w, W0[3], a0);  b0 = hfma2(hC.x, W0[8], b0);
    a1 = hfma2(hA.w, W1[3], a1);  b1 = hfma2(hC.x, W1[8], b1);
    a0 = hfma2(hB.x, W0[4], a0);  b0 = hfma2(hC.y, W0[9], b0);
    a1 = hfma2(hB.x, W1[4], a1);  b1 = hfma2(hC.y, W1[9], b1);

    u32 A = hadd2(a0, b0);          // {p, q}
    u32 B = hadd2(a1, b1);          // {r, s}
    u32 C = prmt(A, B, 0x5410);     // {p, r}
    u32 D = prmt(A, B, 0x7632);     // {q, s}
    u32 E = hadd2(C, D);            // {o0pre, o1pre}
    u32 hn = tanh2(E);

    dst[sOff] = hn;                 // unconditional STS.32
}

__global__ void __launch_bounds__(CTA_THREADS, 1)
rnn_tanh_kernel(
    const float* __restrict__ x,     const float* __restrict__ h0,
    const float* __restrict__ W_ih,  const float* __restrict__ W_hh,
    const float* __restrict__ b_ih,  const float* __restrict__ b_hh,
    const float* __restrict__ fc_w,  const float* __restrict__ fc_b,
    float* __restrict__ out)
{
    __shared__ __align__(16) u32 sm[WARPS_CTA][2][40];

    const int lane = threadIdx.x & 31;
    const int w    = threadIdx.x >> 5;
    const int gw   = blockIdx.x * WARPS_CTA + w;
    if (gw * 3 >= B_TOTAL) return;

    const bool live = (lane < 30);
    const int  g    = live ? (lane / 10) : 2;
    const int  p    = live ? (lane % 10) : (lane - 30);
    const int  b    = gw * 3 + g;
    const int  bc   = (b < B_TOTAL) ? b : (B_TOTAL - 1);
    const int  o0   = 2 * p;
    const int  sOff = live ? (g * HSTRIDE + p) : (38 + (lane - 30));

    // ---- per-thread weights: fp16x2 packed over j ----
    u32 W0[10], W1[10];
    #pragma unroll
    for (int q = 0; q < 10; q++) {
        W0[q] = cvt2h(__ldg(&W_hh[o0 * H_DIM + 2 * q + 1]),
                      __ldg(&W_hh[o0 * H_DIM + 2 * q]));
        W1[q] = cvt2h(__ldg(&W_hh[(o0 + 1) * H_DIM + 2 * q + 1]),
                      __ldg(&W_hh[(o0 + 1) * H_DIM + 2 * q]));
    }
    const u32 Wi0a = cvt2h(__ldg(&W_ih[o0 * 4 + 1]), __ldg(&W_ih[o0 * 4 + 0]));
    const u32 Wi0b = cvt2h(__ldg(&W_ih[o0 * 4 + 3]), __ldg(&W_ih[o0 * 4 + 2]));
    const u32 Wi1a = cvt2h(__ldg(&W_ih[(o0 + 1) * 4 + 1]), __ldg(&W_ih[(o0 + 1) * 4 + 0]));
    const u32 Wi1b = cvt2h(__ldg(&W_ih[(o0 + 1) * 4 + 3]), __ldg(&W_ih[(o0 + 1) * 4 + 2]));
    const u32 seed0 = cvt2h(0.f, __ldg(&b_ih[o0])     + __ldg(&b_hh[o0]));
    const u32 seed1 = cvt2h(0.f, __ldg(&b_ih[o0 + 1]) + __ldg(&b_hh[o0 + 1]));

    u32* bufA = &sm[w][0][0];
    u32* bufB = &sm[w][1][0];

    // ---- init h (fp16x2) into buffer A ----
    {
        const float2* h2 = reinterpret_cast<const float2*>(h0);
        float2 hv = __ldg(&h2[bc * (H_DIM / 2) + p]);
        bufA[sOff] = cvt2h(hv.y, hv.x);
    }
    __syncwarp();

    // ---- phase stagger: dependent-FMA delay ~30*w cycles to de-convoy warps ----
    {
        float d = 1.0f + (float)w;
        for (int i = 0; i < w * 4; i++) {
            d = fmaf(d, 1.0000001f, 1e-7f);
            d = fmaf(d, 0.9999999f, 1e-7f);
        }
        asm volatile("" :: "f"(d));   // sink, keeps the chain, no side effect
    }

    const ulonglong2* xp = reinterpret_cast<const ulonglong2*>(x) + (size_t)bc * T_STEPS;
    ulonglong2 xbuf[PF];
    #pragma unroll
    for (int q = 0; q < PF; q++) xbuf[q] = __ldg(&xp[q]);

    for (int t = 0; t < T_STEPS - PF; t += PF) {
        #pragma unroll
        for (int q = 0; q < PF; q++) {
            ulonglong2 xv = xbuf[q];
            xbuf[q] = __ldg(&xp[t + q + PF]);
            if (q & 1)
                rnn_step(bufB, bufA, g, sOff, xv, W0, W1, Wi0a, Wi0b, Wi1a, Wi1b, seed0, seed1);
            else
                rnn_step(bufA, bufB, g, sOff, xv, W0, W1, Wi0a, Wi0b, Wi1a, Wi1b, seed0, seed1);
        }
    }
    #pragma unroll
    for (int q = 0; q < PF; q++) {
        if (q & 1)
            rnn_step(bufB, bufA, g, sOff, xbuf[q], W0, W1, Wi0a, Wi0b, Wi1a, Wi1b, seed0, seed1);
        else
            rnn_step(bufA, bufB, g, sOff, xbuf[q], W0, W1, Wi0a, Wi0b, Wi1a, Wi1b, seed0, seed1);
    }

    // Final h in bufA (T_STEPS even). Linear head in fp32 from fp16 h.
    __syncwarp();
    if (live && p < O_DIM && b < B_TOTAL) {
        const u32* hb = bufA + g * HSTRIDE;
        float acc = __ldg(&fc_b[p]);
        #pragma unroll
        for (int q = 0; q < 10; q++) {
            float2 hv = __half22float2(*reinterpret_cast<const __half2*>(&hb[q]));
            acc = fmaf(hv.x, __ldg(&fc_w[p * H_DIM + 2 * q]),     acc);
            acc = fmaf(hv.y, __ldg(&fc_w[p * H_DIM + 2 * q + 1]), acc);
        }
        out[b * O_DIM + p] = acc;
    }
}

extern "C" void kernel_launch(void* const* d_in, const int* in_sizes, int n_in,
                              void* d_out, int out_size)
{
    const float* x    = (const float*)d_in[0];
    const float* h0   = (const float*)d_in[1];
    const float* W_ih = (const float*)d_in[2];
    const float* W_hh = (const float*)d_in[3];
    const float* b_ih = (const float*)d_in[4];
    const float* b_hh = (const float*)d_in[5];
    const float* fc_w = (const float*)d_in[6];
    const float* fc_b = (const float*)d_in[7];
    float* out = (float*)d_out;

    rnn_tanh_kernel<<<GRID, CTA_THREADS>>>(x, h0, W_ih, W_hh, b_ih, b_hh,
                                           fc_w, fc_b, out);
}